// round 5
// baseline (speedup 1.0000x reference)
#include <cuda_runtime.h>
#include <cuda_bf16.h>
#include <math.h>

// Problem constants (fixed by the dataset)
#define D        512
#define MAX_B    128
#define MAX_M    6304
#define MAXK     64
#define KSPLIT   2
#define KHALF    (D / KSPLIT)          // 256

// ---------------- scratch (no allocations allowed) ----------------
__device__ float g_cosP[KSPLIT * MAX_B * MAX_M]; // split-K partial cos sims
__device__ float g_qinv[MAX_B];          // 1/max(||q||, eps)
__device__ float g_minv[MAX_M];          // 1/max(||mem||, eps)
__device__ int   g_idx[MAX_B * MAXK];    // top-k block indices
__device__ float g_wgt[MAX_B * MAXK];    // softmax weights * scalar weight

// ---------------- Kernel 1: inverse norms ----------------
__global__ void norm_kernel(const float* __restrict__ q,
                            const float* __restrict__ mem, int B) {
    int r = blockIdx.x;
    const float* src = (r < B) ? (q + (long)r * D) : (mem + (long)(r - B) * D);
    float4 v = ((const float4*)src)[threadIdx.x];
    float ss = v.x * v.x + v.y * v.y + v.z * v.z + v.w * v.w;
    #pragma unroll
    for (int o = 16; o; o >>= 1) ss += __shfl_xor_sync(0xffffffffu, ss, o);
    __shared__ float sred[4];
    if ((threadIdx.x & 31) == 0) sred[threadIdx.x >> 5] = ss;
    __syncthreads();
    if (threadIdx.x == 0) {
        float t = sred[0] + sred[1] + sred[2] + sred[3];
        float inv = 1.0f / fmaxf(sqrtf(t), 1e-8f);
        if (r < B) g_qinv[r] = inv;
        else       g_minv[r - B] = inv;
    }
}

// ---------------- Kernel 2: split-K cos-sim GEMM ----------------
// Partial[z][b][m] = sum_{d in z-th K half} Qn[b][d]*Mn[m][d], scaled by norms.
// Block tile: 64 b x 32 m, 128 threads, 4x4 register tile.
// grid = (M/32, B/64, KSPLIT).
__global__ void cos_gemm_kernel(const float* __restrict__ q,
                                const float* __restrict__ mem, int M) {
    __shared__ float sQ[32][68];
    __shared__ float sM[32][36];

    int tid = threadIdx.x;
    int tx = tid & 7;
    int ty = tid >> 3;
    int m0 = blockIdx.x * 32;
    int b0 = blockIdx.y * 64;
    int k0 = blockIdx.z * KHALF;

    float acc[4][4];
    #pragma unroll
    for (int i = 0; i < 4; i++)
        #pragma unroll
        for (int j = 0; j < 4; j++) acc[i][j] = 0.0f;

    for (int dc = k0; dc < k0 + KHALF; dc += 32) {
        #pragma unroll
        for (int i = 0; i < 16; i++) {
            int e = tid + i * 128;
            int d = e & 31, bb = e >> 5;
            sQ[d][bb] = q[(long)(b0 + bb) * D + dc + d];
        }
        #pragma unroll
        for (int i = 0; i < 8; i++) {
            int e = tid + i * 128;
            int d = e & 31, mm = e >> 5;
            sM[d][mm] = mem[(long)(m0 + mm) * D + dc + d];
        }
        __syncthreads();
        #pragma unroll
        for (int d = 0; d < 32; d++) {
            float4 a = *(const float4*)&sQ[d][ty * 4];
            float4 bv = *(const float4*)&sM[d][tx * 4];
            float av[4] = {a.x, a.y, a.z, a.w};
            float bvv[4] = {bv.x, bv.y, bv.z, bv.w};
            #pragma unroll
            for (int i = 0; i < 4; i++)
                #pragma unroll
                for (int j = 0; j < 4; j++)
                    acc[i][j] = fmaf(av[i], bvv[j], acc[i][j]);
        }
        __syncthreads();
    }

    float qi[4], mi[4];
    #pragma unroll
    for (int i = 0; i < 4; i++) qi[i] = g_qinv[b0 + ty * 4 + i];
    #pragma unroll
    for (int j = 0; j < 4; j++) mi[j] = g_minv[m0 + tx * 4 + j];
    float* outp = g_cosP + (long)blockIdx.z * MAX_B * MAX_M;
    #pragma unroll
    for (int i = 0; i < 4; i++) {
        long base = (long)(b0 + ty * 4 + i) * M + m0 + tx * 4;
        #pragma unroll
        for (int j = 0; j < 4; j++)
            outp[base + j] = acc[i][j] * qi[i] * mi[j];
    }
}

// ---------------- Kernel 3: top-k via MSB radix select + softmax ------------
// 512 threads. Fuses the split-K add while mapping values.
#define TKT 512
__device__ __forceinline__ unsigned map_f(float f) {
    unsigned u = __float_as_uint(f);
    return (u & 0x80000000u) ? ~u : (u | 0x80000000u);
}
__device__ __forceinline__ float unmap_f(unsigned m) {
    unsigned u = (m & 0x80000000u) ? (m ^ 0x80000000u) : ~m;
    return __uint_as_float(u);
}

__global__ void topk_kernel(const float* __restrict__ wscalar,
                            const int* __restrict__ kp, int M) {
    __shared__ unsigned mv[MAX_M];       // mapped (order-preserving) values
    __shared__ int hist[256];
    __shared__ int warpsum[TKT / 32];
    __shared__ int warpoff[TKT / 32];
    __shared__ unsigned s_pref;
    __shared__ int s_kneed;
    __shared__ int s_totGT;
    __shared__ float topv[MAXK];
    __shared__ int   topi[MAXK];

    int b = blockIdx.x;
    int tid = threadIdx.x;
    int lane = tid & 31, wrp = tid >> 5;
    const float* rowA = g_cosP + (long)b * M;
    const float* rowB = g_cosP + (long)MAX_B * MAX_M + (long)b * M;

    for (int i = tid; i < M; i += TKT) mv[i] = map_f(rowA[i] + rowB[i]);

    int k = kp ? *kp : 50;
    if (k > MAXK) k = MAXK;
    if (k < 1) k = 1;

    if (tid == 0) { s_pref = 0u; s_kneed = k; }
    __syncthreads();

    // 4 radix passes, MSB first: exact kth-largest mapped value.
    for (int shift = 24; shift >= 0; shift -= 8) {
        if (tid < 256) hist[tid] = 0;
        __syncthreads();
        unsigned dmask = (shift == 24) ? 0u : (0xFFFFFFFFu << (shift + 8));
        unsigned pref = s_pref;
        for (int i = tid; i < M; i += TKT) {
            unsigned v = mv[i];
            if ((v & dmask) == pref) atomicAdd(&hist[(v >> shift) & 255], 1);
        }
        __syncthreads();
        if (tid < 32) {
            int s = 0;
            #pragma unroll
            for (int j = 0; j < 8; j++) s += hist[tid * 8 + j];
            int suf = s;
            #pragma unroll
            for (int o = 1; o < 32; o <<= 1) {
                int u = __shfl_down_sync(0xffffffffu, suf, o);
                if (tid + o < 32) suf += u;
            }
            int sufNext = __shfl_down_sync(0xffffffffu, suf, 1);
            if (tid == 31) sufNext = 0;
            int kneed = s_kneed;
            if (kneed <= suf && kneed > sufNext) {   // unique crossing lane
                int c = sufNext;
                #pragma unroll
                for (int d = 7; d >= 0; d--) {
                    int bin = tid * 8 + d;
                    c += hist[bin];
                    if (c >= kneed) {
                        s_kneed = kneed - (c - hist[bin]);
                        s_pref  = pref | ((unsigned)bin << shift);
                        break;
                    }
                }
            }
        }
        __syncthreads();
    }

    unsigned T = s_pref;   // kth largest mapped value

    // Deterministic compaction: count, block-scan, write by rank.
    int cntGT = 0, cntEQ = 0;
    for (int i = tid; i < M; i += TKT) {
        unsigned v = mv[i];
        cntGT += (v > T);
        cntEQ += (v == T);
    }
    int packed = cntGT | (cntEQ << 16);
    int v = packed;
    #pragma unroll
    for (int o = 1; o < 32; o <<= 1) {
        int u = __shfl_up_sync(0xffffffffu, v, o);
        if (lane >= o) v += u;
    }
    if (lane == 31) warpsum[wrp] = v;
    __syncthreads();
    if (tid == 0) {
        int acc = 0;
        #pragma unroll
        for (int w = 0; w < TKT / 32; w++) { warpoff[w] = acc; acc += warpsum[w]; }
        s_totGT = acc & 0xffff;
    }
    __syncthreads();
    int ex = v - packed + warpoff[wrp];       // exclusive packed prefix
    int gtPos = ex & 0xffff;
    int eqPos = s_totGT + (ex >> 16);
    for (int i = tid; i < M; i += TKT) {
        unsigned val = mv[i];
        if (val > T) {
            topi[gtPos] = i; topv[gtPos] = unmap_f(val); gtPos++;
        } else if (val == T) {
            if (eqPos < k) { topi[eqPos] = i; topv[eqPos] = unmap_f(val); }
            eqPos++;
        }
    }
    __syncthreads();

    if (tid == 0) {
        float mx = topv[0];
        for (int j = 1; j < k; j++) mx = fmaxf(mx, topv[j]);
        float s = 0.0f;
        for (int j = 0; j < k; j++) { float e = expf(topv[j] - mx); topv[j] = e; s += e; }
        float w = wscalar[0];
        float inv = w / s;                 // fold scalar blend weight
        for (int j = 0; j < k; j++) {
            g_wgt[b * MAXK + j] = topv[j] * inv;
            g_idx[b * MAXK + j] = topi[j];
        }
    }
}

// ---------------- Kernel 4: gather + weighted reduce + blend ----------------
// grid = (B, nvec/256): batch is the FAST grid dimension so all 128 batches
// of the same position-slice are resident together -> cross-batch L2 reuse.
__global__ void gather_kernel(const float4* __restrict__ fp,
                              const float4* __restrict__ enc,
                              const float* __restrict__ wscalar,
                              const int* __restrict__ kp,
                              float4* __restrict__ out, int nvec) {
    __shared__ int   sidx[MAXK];
    __shared__ float sw[MAXK];
    int b = blockIdx.x;
    int k = kp ? *kp : 50;
    if (k > MAXK) k = MAXK;
    if (k < 1) k = 1;
    if (threadIdx.x < k) {
        sidx[threadIdx.x] = g_idx[b * MAXK + threadIdx.x];
        sw[threadIdx.x]   = g_wgt[b * MAXK + threadIdx.x];
    }
    __syncthreads();

    int pos = blockIdx.y * blockDim.x + threadIdx.x;
    if (pos >= nvec) return;

    float ax = 0.f, ay = 0.f, az = 0.f, aw = 0.f;
    int j = 0;
    for (; j + 4 <= k; j += 4) {
        float4 v0 = fp[(long)sidx[j + 0] * nvec + pos];
        float4 v1 = fp[(long)sidx[j + 1] * nvec + pos];
        float4 v2 = fp[(long)sidx[j + 2] * nvec + pos];
        float4 v3 = fp[(long)sidx[j + 3] * nvec + pos];
        float w0 = sw[j + 0], w1 = sw[j + 1], w2 = sw[j + 2], w3 = sw[j + 3];
        ax = fmaf(w0, v0.x, ax); ay = fmaf(w0, v0.y, ay);
        az = fmaf(w0, v0.z, az); aw = fmaf(w0, v0.w, aw);
        ax = fmaf(w1, v1.x, ax); ay = fmaf(w1, v1.y, ay);
        az = fmaf(w1, v1.z, az); aw = fmaf(w1, v1.w, aw);
        ax = fmaf(w2, v2.x, ax); ay = fmaf(w2, v2.y, ay);
        az = fmaf(w2, v2.z, az); aw = fmaf(w2, v2.w, aw);
        ax = fmaf(w3, v3.x, ax); ay = fmaf(w3, v3.y, ay);
        az = fmaf(w3, v3.z, az); aw = fmaf(w3, v3.w, aw);
    }
    for (; j < k; j++) {
        float4 vv = fp[(long)sidx[j] * nvec + pos];
        float w = sw[j];
        ax = fmaf(w, vv.x, ax); ay = fmaf(w, vv.y, ay);
        az = fmaf(w, vv.z, az); aw = fmaf(w, vv.w, aw);
    }
    float om = 1.0f - wscalar[0];
    float4 e = enc[(long)b * nvec + pos];
    float4 r;
    r.x = fmaf(om, e.x, ax);
    r.y = fmaf(om, e.y, ay);
    r.z = fmaf(om, e.z, az);
    r.w = fmaf(om, e.w, aw);
    out[(long)b * nvec + pos] = r;
}

// ---------------- launch ----------------
extern "C" void kernel_launch(void* const* d_in, const int* in_sizes, int n_in,
                              void* d_out, int out_size) {
    const float* enc = (const float*)d_in[0];
    const float* q   = (const float*)d_in[1];
    const float* mem = (const float*)d_in[2];
    const float* fp  = (const float*)d_in[3];
    const float* wt  = (const float*)d_in[4];
    const int*   kp  = (n_in > 5) ? (const int*)d_in[5] : nullptr;

    int B = in_sizes[1] / D;                // 128
    int M = in_sizes[2] / D;                // 6304
    int blk = in_sizes[0] / (B * D);        // 64
    int nvec = blk * D / 4;                 // 8192 float4 per batch

    norm_kernel<<<B + M, 128>>>(q, mem, B);

    dim3 ggrid(M / 32, B / 64, KSPLIT);
    cos_gemm_kernel<<<ggrid, 128>>>(q, mem, M);

    topk_kernel<<<B, TKT>>>(wt, kp, M);

    dim3 grgrid(B, (nvec + 255) / 256);     // batch fastest -> L2 reuse
    gather_kernel<<<grgrid, 256>>>((const float4*)fp, (const float4*)enc,
                                   wt, kp, (float4*)d_out, nvec);
}

// round 9
// speedup vs baseline: 1.2512x; 1.2512x over previous
#include <cuda_runtime.h>
#include <cuda_bf16.h>
#include <math.h>

// Problem constants (fixed by the dataset)
#define D        512
#define MAX_B    128
#define MAX_M    6304
#define MAXK     64

// ---------------- scratch (no allocations allowed) ----------------
__device__ float g_cos[MAX_B * MAX_M];   // cosine similarities [B, M]
__device__ float g_qinv[MAX_B];          // 1/max(||q||, eps)
__device__ float g_minv[MAX_M];          // 1/max(||mem||, eps)
__device__ int   g_idx[MAX_B * MAXK];    // top-k block indices
__device__ float g_wgt[MAX_B * MAXK];    // softmax weights * scalar weight

// ---------------- Kernel 1: inverse norms ----------------
__global__ void norm_kernel(const float* __restrict__ q,
                            const float* __restrict__ mem, int B) {
    int r = blockIdx.x;
    const float* src = (r < B) ? (q + (long)r * D) : (mem + (long)(r - B) * D);
    float4 v = ((const float4*)src)[threadIdx.x];
    float ss = v.x * v.x + v.y * v.y + v.z * v.z + v.w * v.w;
    #pragma unroll
    for (int o = 16; o; o >>= 1) ss += __shfl_xor_sync(0xffffffffu, ss, o);
    __shared__ float sred[4];
    if ((threadIdx.x & 31) == 0) sred[threadIdx.x >> 5] = ss;
    __syncthreads();
    if (threadIdx.x == 0) {
        float t = sred[0] + sred[1] + sred[2] + sred[3];
        float inv = 1.0f / fmaxf(sqrtf(t), 1e-8f);
        if (r < B) g_qinv[r] = inv;
        else       g_minv[r - B] = inv;
    }
}

// ---------------- Kernel 2: cos-sim GEMM [B,M] = Qn @ Mn^T ----------------
// Block tile: 64 b x 32 m, 128 threads, 4x4 register tile per thread.
// Double-buffered smem with register staging + float4 global loads:
// next chunk's LDG.128s are in flight while current chunk computes.
__global__ void cos_gemm_kernel(const float* __restrict__ q,
                                const float* __restrict__ mem, int M) {
    __shared__ float sQ[2][32][68];   // [buf][d][b]
    __shared__ float sM[2][32][36];   // [buf][d][m]

    int tid = threadIdx.x;                 // 0..127
    int tx = tid & 7;                      // m group
    int ty = tid >> 3;                     // b group
    int m0 = blockIdx.x * 32;
    int b0 = blockIdx.y * 64;

    // Per-chunk load ownership (fixed for all chunks):
    // Q chunk: 64 rows x 8 float4 -> 512 float4, 4 per thread.
    // M chunk: 32 rows x 8 float4 -> 256 float4, 2 per thread.
    int qrow[4], qcol[4], mrow[2], mcol[2];
    #pragma unroll
    for (int i = 0; i < 4; i++) {
        int e = tid + i * 128;
        qrow[i] = e >> 3; qcol[i] = e & 7;
    }
    #pragma unroll
    for (int i = 0; i < 2; i++) {
        int e = tid + i * 128;
        mrow[i] = e >> 3; mcol[i] = e & 7;
    }

    float4 rq[4], rm[2];

    #define LOADG(dc)                                                        \
        do {                                                                 \
            _Pragma("unroll")                                                \
            for (int i = 0; i < 4; i++)                                      \
                rq[i] = *(const float4*)&q[(long)(b0 + qrow[i]) * D + (dc) + qcol[i] * 4]; \
            _Pragma("unroll")                                                \
            for (int i = 0; i < 2; i++)                                      \
                rm[i] = *(const float4*)&mem[(long)(m0 + mrow[i]) * D + (dc) + mcol[i] * 4]; \
        } while (0)

    #define STORES(buf)                                                      \
        do {                                                                 \
            _Pragma("unroll")                                                \
            for (int i = 0; i < 4; i++) {                                    \
                sQ[buf][qcol[i] * 4 + 0][qrow[i]] = rq[i].x;                 \
                sQ[buf][qcol[i] * 4 + 1][qrow[i]] = rq[i].y;                 \
                sQ[buf][qcol[i] * 4 + 2][qrow[i]] = rq[i].z;                 \
                sQ[buf][qcol[i] * 4 + 3][qrow[i]] = rq[i].w;                 \
            }                                                                \
            _Pragma("unroll")                                                \
            for (int i = 0; i < 2; i++) {                                    \
                sM[buf][mcol[i] * 4 + 0][mrow[i]] = rm[i].x;                 \
                sM[buf][mcol[i] * 4 + 1][mrow[i]] = rm[i].y;                 \
                sM[buf][mcol[i] * 4 + 2][mrow[i]] = rm[i].z;                 \
                sM[buf][mcol[i] * 4 + 3][mrow[i]] = rm[i].w;                 \
            }                                                                \
        } while (0)

    float acc[4][4];
    #pragma unroll
    for (int i = 0; i < 4; i++)
        #pragma unroll
        for (int j = 0; j < 4; j++) acc[i][j] = 0.0f;

    LOADG(0);
    STORES(0);
    __syncthreads();

    #pragma unroll 1
    for (int it = 0; it < 16; it++) {
        int cur = it & 1;
        if (it < 15) LOADG((it + 1) * 32);   // LDGs overlap with compute below
        #pragma unroll
        for (int d = 0; d < 32; d++) {
            float4 a = *(const float4*)&sQ[cur][d][ty * 4];
            float4 bv = *(const float4*)&sM[cur][d][tx * 4];
            float av[4] = {a.x, a.y, a.z, a.w};
            float bvv[4] = {bv.x, bv.y, bv.z, bv.w};
            #pragma unroll
            for (int i = 0; i < 4; i++)
                #pragma unroll
                for (int j = 0; j < 4; j++)
                    acc[i][j] = fmaf(av[i], bvv[j], acc[i][j]);
        }
        if (it < 15) {
            STORES(cur ^ 1);
            __syncthreads();
        }
    }

    float qi[4], mi[4];
    #pragma unroll
    for (int i = 0; i < 4; i++) qi[i] = g_qinv[b0 + ty * 4 + i];
    #pragma unroll
    for (int j = 0; j < 4; j++) mi[j] = g_minv[m0 + tx * 4 + j];
    #pragma unroll
    for (int i = 0; i < 4; i++) {
        long base = (long)(b0 + ty * 4 + i) * M + m0 + tx * 4;
        #pragma unroll
        for (int j = 0; j < 4; j++)
            g_cos[base + j] = acc[i][j] * qi[i] * mi[j];
    }
    #undef LOADG
    #undef STORES
}

// ---------------- Kernel 3: top-k via MSB radix select + softmax ------------
#define TKT 512
__device__ __forceinline__ unsigned map_f(float f) {
    unsigned u = __float_as_uint(f);
    return (u & 0x80000000u) ? ~u : (u | 0x80000000u);
}
__device__ __forceinline__ float unmap_f(unsigned m) {
    unsigned u = (m & 0x80000000u) ? (m ^ 0x80000000u) : ~m;
    return __uint_as_float(u);
}

__global__ void topk_kernel(const float* __restrict__ wscalar,
                            const int* __restrict__ kp, int M) {
    __shared__ unsigned mv[MAX_M];       // mapped (order-preserving) values
    __shared__ int hist[256];
    __shared__ int warpsum[TKT / 32];
    __shared__ int warpoff[TKT / 32];
    __shared__ unsigned s_pref;
    __shared__ int s_kneed;
    __shared__ int s_totGT;
    __shared__ float topv[MAXK];
    __shared__ int   topi[MAXK];

    int b = blockIdx.x;
    int tid = threadIdx.x;
    int lane = tid & 31, wrp = tid >> 5;
    const float* row = g_cos + (long)b * M;

    for (int i = tid; i < M; i += TKT) mv[i] = map_f(row[i]);

    int k = kp ? *kp : 50;
    if (k > MAXK) k = MAXK;
    if (k < 1) k = 1;

    if (tid == 0) { s_pref = 0u; s_kneed = k; }
    __syncthreads();

    // 4 radix passes, MSB first: exact kth-largest mapped value.
    for (int shift = 24; shift >= 0; shift -= 8) {
        if (tid < 256) hist[tid] = 0;
        __syncthreads();
        unsigned dmask = (shift == 24) ? 0u : (0xFFFFFFFFu << (shift + 8));
        unsigned pref = s_pref;
        for (int i = tid; i < M; i += TKT) {
            unsigned v = mv[i];
            if ((v & dmask) == pref) atomicAdd(&hist[(v >> shift) & 255], 1);
        }
        __syncthreads();
        if (tid < 32) {
            int s = 0;
            #pragma unroll
            for (int j = 0; j < 8; j++) s += hist[tid * 8 + j];
            int suf = s;
            #pragma unroll
            for (int o = 1; o < 32; o <<= 1) {
                int u = __shfl_down_sync(0xffffffffu, suf, o);
                if (tid + o < 32) suf += u;
            }
            int sufNext = __shfl_down_sync(0xffffffffu, suf, 1);
            if (tid == 31) sufNext = 0;
            int kneed = s_kneed;
            if (kneed <= suf && kneed > sufNext) {   // unique crossing lane
                int c = sufNext;
                #pragma unroll
                for (int d = 7; d >= 0; d--) {
                    int bin = tid * 8 + d;
                    c += hist[bin];
                    if (c >= kneed) {
                        s_kneed = kneed - (c - hist[bin]);
                        s_pref  = pref | ((unsigned)bin << shift);
                        break;
                    }
                }
            }
        }
        __syncthreads();
    }

    unsigned T = s_pref;   // kth largest mapped value

    // Deterministic compaction: count, block-scan, write by rank.
    int cntGT = 0, cntEQ = 0;
    for (int i = tid; i < M; i += TKT) {
        unsigned v = mv[i];
        cntGT += (v > T);
        cntEQ += (v == T);
    }
    int packed = cntGT | (cntEQ << 16);
    int v = packed;
    #pragma unroll
    for (int o = 1; o < 32; o <<= 1) {
        int u = __shfl_up_sync(0xffffffffu, v, o);
        if (lane >= o) v += u;
    }
    if (lane == 31) warpsum[wrp] = v;
    __syncthreads();
    if (tid == 0) {
        int acc = 0;
        #pragma unroll
        for (int w = 0; w < TKT / 32; w++) { warpoff[w] = acc; acc += warpsum[w]; }
        s_totGT = acc & 0xffff;
    }
    __syncthreads();
    int ex = v - packed + warpoff[wrp];       // exclusive packed prefix
    int gtPos = ex & 0xffff;
    int eqPos = s_totGT + (ex >> 16);
    for (int i = tid; i < M; i += TKT) {
        unsigned val = mv[i];
        if (val > T) {
            topi[gtPos] = i; topv[gtPos] = unmap_f(val); gtPos++;
        } else if (val == T) {
            if (eqPos < k) { topi[eqPos] = i; topv[eqPos] = unmap_f(val); }
            eqPos++;
        }
    }
    __syncthreads();

    if (tid == 0) {
        float mx = topv[0];
        for (int j = 1; j < k; j++) mx = fmaxf(mx, topv[j]);
        float s = 0.0f;
        for (int j = 0; j < k; j++) { float e = expf(topv[j] - mx); topv[j] = e; s += e; }
        float w = wscalar[0];
        float inv = w / s;                 // fold scalar blend weight
        for (int j = 0; j < k; j++) {
            g_wgt[b * MAXK + j] = topv[j] * inv;
            g_idx[b * MAXK + j] = topi[j];
        }
    }
}

// ---------------- Kernel 4: gather + weighted reduce + blend ----------------
// grid = (B, nvec/256): batch is the FAST grid dimension so all 128 batches
// of the same position-slice are resident together -> cross-batch L2 reuse.
__global__ void gather_kernel(const float4* __restrict__ fp,
                              const float4* __restrict__ enc,
                              const float* __restrict__ wscalar,
                              const int* __restrict__ kp,
                              float4* __restrict__ out, int nvec) {
    __shared__ int   sidx[MAXK];
    __shared__ float sw[MAXK];
    int b = blockIdx.x;
    int k = kp ? *kp : 50;
    if (k > MAXK) k = MAXK;
    if (k < 1) k = 1;
    if (threadIdx.x < k) {
        sidx[threadIdx.x] = g_idx[b * MAXK + threadIdx.x];
        sw[threadIdx.x]   = g_wgt[b * MAXK + threadIdx.x];
    }
    __syncthreads();

    int pos = blockIdx.y * blockDim.x + threadIdx.x;
    if (pos >= nvec) return;

    float ax = 0.f, ay = 0.f, az = 0.f, aw = 0.f;
    int j = 0;
    for (; j + 4 <= k; j += 4) {
        float4 v0 = fp[(long)sidx[j + 0] * nvec + pos];
        float4 v1 = fp[(long)sidx[j + 1] * nvec + pos];
        float4 v2 = fp[(long)sidx[j + 2] * nvec + pos];
        float4 v3 = fp[(long)sidx[j + 3] * nvec + pos];
        float w0 = sw[j + 0], w1 = sw[j + 1], w2 = sw[j + 2], w3 = sw[j + 3];
        ax = fmaf(w0, v0.x, ax); ay = fmaf(w0, v0.y, ay);
        az = fmaf(w0, v0.z, az); aw = fmaf(w0, v0.w, aw);
        ax = fmaf(w1, v1.x, ax); ay = fmaf(w1, v1.y, ay);
        az = fmaf(w1, v1.z, az); aw = fmaf(w1, v1.w, aw);
        ax = fmaf(w2, v2.x, ax); ay = fmaf(w2, v2.y, ay);
        az = fmaf(w2, v2.z, az); aw = fmaf(w2, v2.w, aw);
        ax = fmaf(w3, v3.x, ax); ay = fmaf(w3, v3.y, ay);
        az = fmaf(w3, v3.z, az); aw = fmaf(w3, v3.w, aw);
    }
    for (; j < k; j++) {
        float4 vv = fp[(long)sidx[j] * nvec + pos];
        float w = sw[j];
        ax = fmaf(w, vv.x, ax); ay = fmaf(w, vv.y, ay);
        az = fmaf(w, vv.z, az); aw = fmaf(w, vv.w, aw);
    }
    float om = 1.0f - wscalar[0];
    float4 e = enc[(long)b * nvec + pos];
    float4 r;
    r.x = fmaf(om, e.x, ax);
    r.y = fmaf(om, e.y, ay);
    r.z = fmaf(om, e.z, az);
    r.w = fmaf(om, e.w, aw);
    out[(long)b * nvec + pos] = r;
}

// ---------------- launch ----------------
extern "C" void kernel_launch(void* const* d_in, const int* in_sizes, int n_in,
                              void* d_out, int out_size) {
    const float* enc = (const float*)d_in[0];
    const float* q   = (const float*)d_in[1];
    const float* mem = (const float*)d_in[2];
    const float* fp  = (const float*)d_in[3];
    const float* wt  = (const float*)d_in[4];
    const int*   kp  = (n_in > 5) ? (const int*)d_in[5] : nullptr;

    int B = in_sizes[1] / D;                // 128
    int M = in_sizes[2] / D;                // 6304
    int blk = in_sizes[0] / (B * D);        // 64
    int nvec = blk * D / 4;                 // 8192 float4 per batch

    norm_kernel<<<B + M, 128>>>(q, mem, B);

    dim3 ggrid(M / 32, B / 64);
    cos_gemm_kernel<<<ggrid, 128>>>(q, mem, M);

    topk_kernel<<<B, TKT>>>(wt, kp, M);

    dim3 grgrid(B, (nvec + 255) / 256);     // batch fastest -> L2 reuse
    gather_kernel<<<grgrid, 256>>>((const float4*)fp, (const float4*)enc,
                                   wt, kp, (float4*)d_out, nvec);
}